// round 9
// baseline (speedup 1.0000x reference)
#include <cuda_runtime.h>
#include <cstdint>

// EquiLocalPatOrientConvolution: B=2, I=32, O=64, D=H=W=48, K=5 (pad 2).
// v9 = v8 + separable radial: stage A presums along x (s0/s1/s4 per row),
// stage B gathers 75 (not 125) taps per voxel. All smem stages provably
// bank-conflict-free. mma.sync m16n8k8 tf32 3x-split unchanged.

#define DIMS  48
#define TX    8
#define TY    8
#define TZ    2
#define HX    12
#define HY    12
#define HZ    6
#define XSTR  25                        // xs row stride (float2): 9t+x bijection
#define SSTR  74                        // S column stride (float2): 10vx+vy bijection
#define NI    32
#define NO    64
#define NP    10
#define Y0C   0.28209479177387814f
#define NTHR  128
#define NPAIR 16

#define XS_F2      (HZ * HY * XSTR)     // 1800 float2
#define S_F2       (24 * SSTR)          // 1776 float2 (3 classes x 8 x-cols)
#define YS_STRIDE  136                  // 128 vox + 8 pad
#define YS_FLOATS  (24 * YS_STRIDE)
#define SMEM_FLOATS (2 * XS_F2 + 2 * S_F2 + YS_FLOATS)
#define SMEM_BYTES  (SMEM_FLOATS * 4 + 256)

__device__ __host__ constexpr int p_of_r2(int r2) {
    return r2 <= 6 ? r2 : (r2 == 8 ? 7 : (r2 == 9 ? 8 : 9));
}

// B fragments: [pair][ks][nt][lane] -> float4 {b0hi, b1hi, b0lo, b1lo}
__device__ float4 g_Bf[NPAIR * 3 * 8 * 32];

__device__ __forceinline__ uint32_t tf32_rna(float x) {
    uint32_t r;
    asm("cvt.rna.tf32.f32 %0, %1;" : "=r"(r) : "f"(x));
    return r;
}

__device__ __forceinline__ void mma_tf32(float* c,
                                         uint32_t a0, uint32_t a1, uint32_t a2, uint32_t a3,
                                         uint32_t b0, uint32_t b1) {
    asm("mma.sync.aligned.m16n8k8.row.col.f32.tf32.tf32.f32 "
        "{%0,%1,%2,%3}, {%4,%5,%6,%7}, {%8,%9}, {%0,%1,%2,%3};"
        : "+f"(c[0]), "+f"(c[1]), "+f"(c[2]), "+f"(c[3])
        : "r"(a0), "r"(a1), "r"(a2), "r"(a3), "r"(b0), "r"(b1));
}

// ---------- prep: W[o][ci][p] -> B-fragment layout, Y0 folded, hi/lo tf32 ----------
__global__ void bprep_kernel(const float* __restrict__ wg) {
    int idx = blockIdx.x * 256 + threadIdx.x;
    if (idx >= NPAIR * 3 * 8 * 32) return;
    int lane = idx & 31;
    int r    = idx >> 5;
    int nt   = r & 7;  r >>= 3;
    int ks   = r % 3;
    int pair = r / 3;
    int gid = lane >> 2, tidg = lane & 3;
    int o = nt * 8 + gid;
    auto getw = [&](int k) -> float {
        if (k >= 20) return 0.0f;
        int ci = pair * 2 + k / 10;
        int p  = k % 10;
        return Y0C * wg[o * (NI * NP) + ci * NP + p];
    };
    float b0 = getw(ks * 8 + tidg);
    float b1 = getw(ks * 8 + tidg + 4);
    uint32_t b0h = tf32_rna(b0), b1h = tf32_rna(b1);
    uint32_t b0l = tf32_rna(b0 - __uint_as_float(b0h));
    uint32_t b1l = tf32_rna(b1 - __uint_as_float(b1h));
    g_Bf[idx] = make_float4(__uint_as_float(b0h), __uint_as_float(b1h),
                            __uint_as_float(b0l), __uint_as_float(b1l));
}

// ---------- main ----------
__global__ void __launch_bounds__(NTHR, 4)
econv_kernel(const float* __restrict__ x,
             const float* __restrict__ bias,
             float* __restrict__ out)
{
    extern __shared__ float smem[];
    float2* xs = (float2*)smem;                        // [z][y][x], stride XSTR
    float2* S  = xs + XS_F2;                           // [(c*8+x)][z*12+y], stride SSTR
    float*  Ys = smem + 2 * XS_F2 + 2 * S_F2;          // [k][vox], stride YS_STRIDE

    const int tid  = threadIdx.x;
    const int wid  = tid >> 5;
    const int lid  = tid & 31;
    const int gid  = lid >> 2;
    const int tidg = lid & 3;
    const int b    = blockIdx.y;
    const int t    = blockIdx.x;                // 6x6x24
    const int tz   = t / 36;
    const int ty   = (t % 36) / 6;
    const int tx   = t % 6;
    const int z0   = tz * TZ, y0 = ty * TY, x0 = tx * TX;

    const size_t x_chan = (size_t)DIMS * DIMS * DIMS;
    const float* xb = x + (size_t)b * NI * x_chan;

    // zero the K-pad rows (20..23) once
    #pragma unroll
    for (int k = 0; k < 5; k++) {
        int idx = tid + k * NTHR;
        if (idx < 4 * YS_STRIDE) Ys[20 * YS_STRIDE + idx] = 0.0f;
    }

    float acc[64];
    #pragma unroll
    for (int k = 0; k < 64; k++) acc[k] = 0.0f;

    // ---- halo prefetch (864 cells of 12x12x6, 2 channels) ----
    float pre0[7], pre1[7];
    auto pf_x = [&](int pair) {
        const float* c0 = xb + (size_t)(2 * pair) * x_chan;
        const float* c1 = c0 + x_chan;
        #pragma unroll
        for (int k = 0; k < 7; k++) {
            int idx = tid + k * NTHR;
            float v0 = 0.0f, v1 = 0.0f;
            if (idx < HZ * HY * HX) {
                int zz = idx / (HX * HY);
                int rr = idx % (HX * HY);
                int yy = rr / HX, xx = rr % HX;
                int gz = z0 + zz - 2, gy = y0 + yy - 2, gx = x0 + xx - 2;
                if ((unsigned)gz < (unsigned)DIMS &&
                    (unsigned)gy < (unsigned)DIMS &&
                    (unsigned)gx < (unsigned)DIMS) {
                    int off = (gz * DIMS + gy) * DIMS + gx;
                    v0 = __ldg(&c0[off]);
                    v1 = __ldg(&c1[off]);
                }
            }
            pre0[k] = v0; pre1[k] = v1;
        }
    };
    auto cm_x = [&]() {
        #pragma unroll
        for (int k = 0; k < 7; k++) {
            int idx = tid + k * NTHR;
            if (idx < HZ * HY * HX) {
                int zz = idx / (HX * HY);
                int rr = idx % (HX * HY);
                int yy = rr / HX, xx = rr % HX;
                xs[(zz * HY + yy) * XSTR + xx] = make_float2(pre0[k], pre1[k]);
            }
        }
    };

    // ---- stage A: x partial sums per (z,y) row -> S (s0,s1,s4) ----
    auto stageA = [&]() {
        if (tid < HZ * HY) {
            const unsigned long long* row =
                (const unsigned long long*)(xs + tid * XSTR);
            unsigned long long r[12];
            #pragma unroll
            for (int i = 0; i < 12; i++) r[i] = row[i];
            unsigned long long* dst = (unsigned long long*)S + tid;
            #pragma unroll
            for (int xq = 0; xq < 8; xq++) {
                unsigned long long s1, s4;
                asm("add.rn.f32x2 %0, %1, %2;" : "=l"(s1) : "l"(r[xq + 1]), "l"(r[xq + 3]));
                asm("add.rn.f32x2 %0, %1, %2;" : "=l"(s4) : "l"(r[xq]), "l"(r[xq + 4]));
                dst[(0 * 8 + xq) * SSTR] = r[xq + 2];
                dst[(1 * 8 + xq) * SSTR] = s1;
                dst[(2 * 8 + xq) * SSTR] = s4;
            }
        }
    };

    // ---- stage B: 75-tap gather -> Ys (10 classes x 2 channels) ----
    auto stageB = [&]() {
        const int vz = tid >> 6, vy = (tid >> 3) & 7, vx = tid & 7;
        const unsigned long long* s0 = (const unsigned long long*)S + (0 * 8 + vx) * SSTR;
        const unsigned long long* s1 = (const unsigned long long*)S + (1 * 8 + vx) * SSTR;
        const unsigned long long* s4 = (const unsigned long long*)S + (2 * 8 + vx) * SSTR;
        unsigned long long yr[NP];
        #pragma unroll
        for (int p = 0; p < NP; p++) yr[p] = 0ULL;
        #pragma unroll
        for (int dz = 0; dz < 5; dz++) {
            #pragma unroll
            for (int dy = 0; dy < 5; dy++) {
                const int q  = (dz - 2) * (dz - 2) + (dy - 2) * (dy - 2);
                const int zy = (vz + dz) * HY + (vy + dy);
                asm("add.rn.f32x2 %0, %0, %1;"
                    : "+l"(yr[p_of_r2(q)]) : "l"(s0[zy]));
                asm("add.rn.f32x2 %0, %0, %1;"
                    : "+l"(yr[p_of_r2(q + 1)]) : "l"(s1[zy]));
                asm("add.rn.f32x2 %0, %0, %1;"
                    : "+l"(yr[p_of_r2(q + 4)]) : "l"(s4[zy]));
            }
        }
        #pragma unroll
        for (int p = 0; p < NP; p++) {
            float2 v = *(float2*)&yr[p];
            Ys[p * YS_STRIDE + tid]        = v.x;   // ch0 -> k rows 0..9
            Ys[(p + 10) * YS_STRIDE + tid] = v.y;   // ch1 -> k rows 10..19
        }
    };

    // ---- GEMM: 3xTF32 mma over this pair's K=24 (rows 20..23 zero) ----
    auto gemm = [&](int pair) {
        const float4* bsrc = g_Bf + pair * (3 * 8 * 32);
        #pragma unroll
        for (int ks = 0; ks < 3; ks++) {
            float4 bf[8];
            #pragma unroll
            for (int nt = 0; nt < 8; nt++)
                bf[nt] = __ldg(&bsrc[(ks * 8 + nt) * 32 + lid]);
            uint32_t Ah[2][4], Al[2][4];
            #pragma unroll
            for (int mt = 0; mt < 2; mt++) {
                const int vb = wid * 32 + mt * 16 + gid;
                const float* yk = Ys + (ks * 8 + tidg) * YS_STRIDE;
                float a[4];
                a[0] = yk[vb];
                a[1] = yk[vb + 8];
                a[2] = yk[4 * YS_STRIDE + vb];
                a[3] = yk[4 * YS_STRIDE + vb + 8];
                #pragma unroll
                for (int r = 0; r < 4; r++) {
                    Ah[mt][r] = tf32_rna(a[r]);
                    Al[mt][r] = tf32_rna(a[r] - __uint_as_float(Ah[mt][r]));
                }
            }
            #pragma unroll
            for (int nt = 0; nt < 8; nt++) {
                uint32_t b0h = __float_as_uint(bf[nt].x);
                uint32_t b1h = __float_as_uint(bf[nt].y);
                uint32_t b0l = __float_as_uint(bf[nt].z);
                uint32_t b1l = __float_as_uint(bf[nt].w);
                #pragma unroll
                for (int mt = 0; mt < 2; mt++) {
                    float* c = &acc[(mt * 8 + nt) * 4];
                    mma_tf32(c, Ah[mt][0], Ah[mt][1], Ah[mt][2], Ah[mt][3], b0h, b1h);
                    mma_tf32(c, Al[mt][0], Al[mt][1], Al[mt][2], Al[mt][3], b0h, b1h);
                    mma_tf32(c, Ah[mt][0], Ah[mt][1], Ah[mt][2], Ah[mt][3], b0l, b1l);
                }
            }
        }
    };

    // ---- prologue: build Ys(0) ----
    pf_x(0);
    cm_x();
    __syncthreads();
    stageA();
    __syncthreads();
    stageB();

    // ---- main loop over 16 channel pairs (3 barriers/pair) ----
    #pragma unroll 1
    for (int pair = 0; pair < NPAIR; pair++) {
        if (pair + 1 < NPAIR) pf_x(pair + 1);
        __syncthreads();                 // Ys(pair) ready; xs free for rewrite
        gemm(pair);
        if (pair + 1 < NPAIR) {
            cm_x();
            __syncthreads();             // xs visible; gemm done with Ys
            stageA();
            __syncthreads();             // S visible
            stageB();                    // writes Ys(pair+1)
        }
    }

    // ---- epilogue: stage through smem (aliases Ys) for coalesced stores ----
    __syncthreads();
    float* stage = Ys;
    #pragma unroll 1
    for (int chunk = 0; chunk < 4; chunk++) {
        if (chunk) __syncthreads();
        #pragma unroll
        for (int mt = 0; mt < 2; mt++) {
            #pragma unroll
            for (int nt2 = 0; nt2 < 2; nt2++) {
                const int nt = chunk * 2 + nt2;
                #pragma unroll
                for (int r = 0; r < 4; r++) {
                    int vox = wid * 32 + mt * 16 + gid + ((r >> 1) << 3);
                    int c16 = nt2 * 8 + 2 * tidg + (r & 1);
                    stage[c16 * YS_STRIDE + vox] = acc[(mt * 8 + nt) * 4 + r];
                }
            }
        }
        __syncthreads();
        #pragma unroll
        for (int j = 0; j < 4; j++) {
            const int o16  = j * 4 + wid;
            const int row  = lid >> 1;
            const int half = lid & 1;
            const int o    = chunk * 16 + o16;
            const float bb = __ldg(&bias[o]);
            float4 v = *(float4*)&stage[o16 * YS_STRIDE + row * 8 + half * 4];
            v.x += bb; v.y += bb; v.z += bb; v.w += bb;
            const int gz = z0 + (row >> 3), gy = y0 + (row & 7);
            float* dst = out + ((size_t)b * NO + o) * x_chan
                             + ((size_t)gz * DIMS + gy) * DIMS + x0 + half * 4;
            *(float4*)dst = v;
        }
    }
}

extern "C" void kernel_launch(void* const* d_in, const int* in_sizes, int n_in,
                              void* d_out, int out_size)
{
    const float* x    = (const float*)d_in[0];   // [2,32,1,48,48,48]
    const float* w    = (const float*)d_in[1];   // [64,32,1,1,1,10]
    const float* bias = (const float*)d_in[2];   // [64]
    float* out = (float*)d_out;                  // [2,64,1,48,48,48]

    bprep_kernel<<<(NPAIR * 3 * 8 * 32 + 255) / 256, 256>>>(w);

    dim3 grid(864, 2);   // 6x6x24 spatial tiles x batch
    econv_kernel<<<grid, NTHR, SMEM_BYTES>>>(x, bias, out);
}

// round 10
// speedup vs baseline: 1.0388x; 1.0388x over previous
#include <cuda_runtime.h>
#include <cstdint>

// EquiLocalPatOrientConvolution: B=2, I=32, O=64, D=H=W=48, K=5 (pad 2).
// v10 = v8 (direct conflict-free 125-tap radial, f32x2, 2ch/pass; tf32 3x mma)
// + double-buffered Ys so radial(pair+1) and gemm(pair) share ONE barrier
// region per pair (warps skew across LSU/tensor phases). 4 blocks/SM.

#define DIMS  48
#define TX    8
#define TY    8
#define TZ    2
#define HX    12
#define HY    12
#define HZ    6
#define XSTR  24                        // padded row stride (float2), conflict-free
#define NI    32
#define NO    64
#define NP    10
#define Y0C   0.28209479177387814f
#define NTHR  128
#define NPAIR 16

#define XS_ELEMS   (HZ * HY * XSTR)     // 1728 float2 per buffer
#define YS_STRIDE  136                  // 128 vox + 8 pad
#define YS_ROWS    24                   // k = 0..19 data, 20..23 zero
#define YS_FLOATS  (YS_ROWS * YS_STRIDE)
#define SMEM_FLOATS (2 * 2 * XS_ELEMS + 2 * YS_FLOATS)
#define SMEM_BYTES  (SMEM_FLOATS * 4 + 256)   // ~53.8 KB

__device__ __host__ constexpr int p_of_r2(int r2) {
    return r2 <= 6 ? r2 : (r2 == 8 ? 7 : (r2 == 9 ? 8 : 9));
}

// B fragments: [pair][ks][nt][lane] -> float4 {b0hi, b1hi, b0lo, b1lo}
__device__ float4 g_Bf[NPAIR * 3 * 8 * 32];

__device__ __forceinline__ uint32_t tf32_rna(float x) {
    uint32_t r;
    asm("cvt.rna.tf32.f32 %0, %1;" : "=r"(r) : "f"(x));
    return r;
}

__device__ __forceinline__ void mma_tf32(float* c,
                                         uint32_t a0, uint32_t a1, uint32_t a2, uint32_t a3,
                                         uint32_t b0, uint32_t b1) {
    asm("mma.sync.aligned.m16n8k8.row.col.f32.tf32.tf32.f32 "
        "{%0,%1,%2,%3}, {%4,%5,%6,%7}, {%8,%9}, {%0,%1,%2,%3};"
        : "+f"(c[0]), "+f"(c[1]), "+f"(c[2]), "+f"(c[3])
        : "r"(a0), "r"(a1), "r"(a2), "r"(a3), "r"(b0), "r"(b1));
}

// ---------- prep: W[o][ci][p] -> B-fragment layout, Y0 folded, hi/lo tf32 ----------
__global__ void bprep_kernel(const float* __restrict__ wg) {
    int idx = blockIdx.x * 256 + threadIdx.x;
    if (idx >= NPAIR * 3 * 8 * 32) return;
    int lane = idx & 31;
    int r    = idx >> 5;
    int nt   = r & 7;  r >>= 3;
    int ks   = r % 3;
    int pair = r / 3;
    int gid = lane >> 2, tidg = lane & 3;
    int o = nt * 8 + gid;
    auto getw = [&](int k) -> float {
        if (k >= 20) return 0.0f;
        int ci = pair * 2 + k / 10;
        int p  = k % 10;
        return Y0C * wg[o * (NI * NP) + ci * NP + p];
    };
    float b0 = getw(ks * 8 + tidg);
    float b1 = getw(ks * 8 + tidg + 4);
    uint32_t b0h = tf32_rna(b0), b1h = tf32_rna(b1);
    uint32_t b0l = tf32_rna(b0 - __uint_as_float(b0h));
    uint32_t b1l = tf32_rna(b1 - __uint_as_float(b1h));
    g_Bf[idx] = make_float4(__uint_as_float(b0h), __uint_as_float(b1h),
                            __uint_as_float(b0l), __uint_as_float(b1l));
}

// ---------- main ----------
__global__ void __launch_bounds__(NTHR, 4)
econv_kernel(const float* __restrict__ x,
             const float* __restrict__ bias,
             float* __restrict__ out)
{
    extern __shared__ float smem[];
    float2* xs[2];
    xs[0] = (float2*)smem;
    xs[1] = xs[0] + XS_ELEMS;
    float* ysb[2];
    ysb[0] = smem + 4 * XS_ELEMS;
    ysb[1] = ysb[0] + YS_FLOATS;

    const int tid  = threadIdx.x;
    const int wid  = tid >> 5;
    const int lid  = tid & 31;
    const int gid  = lid >> 2;
    const int tidg = lid & 3;
    const int b    = blockIdx.y;
    const int t    = blockIdx.x;                // 6x6x24
    const int tz   = t / 36;
    const int ty   = (t % 36) / 6;
    const int tx   = t % 6;
    const int z0   = tz * TZ, y0 = ty * TY, x0 = tx * TX;

    const size_t x_chan = (size_t)DIMS * DIMS * DIMS;
    const float* xb = x + (size_t)b * NI * x_chan;

    // zero the K-pad rows (20..23) in both Ys buffers
    #pragma unroll
    for (int k = 0; k < 9; k++) {
        int idx = tid + k * NTHR;
        if (idx < 2 * 4 * YS_STRIDE) {
            int buf = idx / (4 * YS_STRIDE);
            int off = idx % (4 * YS_STRIDE);
            ysb[buf][20 * YS_STRIDE + off] = 0.0f;
        }
    }

    float acc[64];
    #pragma unroll
    for (int k = 0; k < 64; k++) acc[k] = 0.0f;

    // ---- halo prefetch (864 cells of 12x12x6, 2 channels) ----
    float pre0[7], pre1[7];
    auto pf_x = [&](int pair) {
        const float* c0 = xb + (size_t)(2 * pair) * x_chan;
        const float* c1 = c0 + x_chan;
        #pragma unroll
        for (int k = 0; k < 7; k++) {
            int idx = tid + k * NTHR;
            float v0 = 0.0f, v1 = 0.0f;
            if (idx < HZ * HY * HX) {
                int zz = idx / (HX * HY);
                int rr = idx % (HX * HY);
                int yy = rr / HX, xx = rr % HX;
                int gz = z0 + zz - 2, gy = y0 + yy - 2, gx = x0 + xx - 2;
                if ((unsigned)gz < (unsigned)DIMS &&
                    (unsigned)gy < (unsigned)DIMS &&
                    (unsigned)gx < (unsigned)DIMS) {
                    int off = (gz * DIMS + gy) * DIMS + gx;
                    v0 = __ldg(&c0[off]);
                    v1 = __ldg(&c1[off]);
                }
            }
            pre0[k] = v0; pre1[k] = v1;
        }
    };
    auto cm_x = [&](float2* dst) {
        #pragma unroll
        for (int k = 0; k < 7; k++) {
            int idx = tid + k * NTHR;
            if (idx < HZ * HY * HX) {
                int zz = idx / (HX * HY);
                int rr = idx % (HX * HY);
                int yy = rr / HX, xx = rr % HX;
                dst[(zz * HY + yy) * XSTR + xx] = make_float2(pre0[k], pre1[k]);
            }
        }
    };

    // ---- radial sums for 2 channels at once (packed f32x2, conflict-free) ----
    auto radial = [&](const float2* xsrc, float* Ys) {
        const int vz = tid >> 6, vy = (tid >> 3) & 7, vx = tid & 7;
        const unsigned long long* xu = (const unsigned long long*)xsrc;
        unsigned long long yr[NP];
        #pragma unroll
        for (int p = 0; p < NP; p++) yr[p] = 0ULL;
        #pragma unroll
        for (int dz = 0; dz < 5; dz++) {
            #pragma unroll
            for (int dy = 0; dy < 5; dy++) {
                const unsigned long long* row =
                    &xu[((vz + dz) * HY + (vy + dy)) * XSTR + vx];
                #pragma unroll
                for (int dx = 0; dx < 5; dx++) {
                    const int p = p_of_r2((dz - 2) * (dz - 2) +
                                          (dy - 2) * (dy - 2) +
                                          (dx - 2) * (dx - 2));
                    asm("add.rn.f32x2 %0, %0, %1;" : "+l"(yr[p]) : "l"(row[dx]));
                }
            }
        }
        #pragma unroll
        for (int p = 0; p < NP; p++) {
            float2 v = *(float2*)&yr[p];
            Ys[p * YS_STRIDE + tid]        = v.x;   // ch0 -> k rows 0..9
            Ys[(p + 10) * YS_STRIDE + tid] = v.y;   // ch1 -> k rows 10..19
        }
    };

    // ---- GEMM: 3xTF32 mma over this pair's K=24 (rows 20..23 zero) ----
    auto gemm = [&](int pair, const float* Ys) {
        const float4* bsrc = g_Bf + pair * (3 * 8 * 32);
        #pragma unroll
        for (int ks = 0; ks < 3; ks++) {
            float4 bf[8];
            #pragma unroll
            for (int nt = 0; nt < 8; nt++)
                bf[nt] = __ldg(&bsrc[(ks * 8 + nt) * 32 + lid]);
            uint32_t Ah[2][4], Al[2][4];
            #pragma unroll
            for (int mt = 0; mt < 2; mt++) {
                const int vb = wid * 32 + mt * 16 + gid;
                const float* yk = Ys + (ks * 8 + tidg) * YS_STRIDE;
                float a[4];
                a[0] = yk[vb];
                a[1] = yk[vb + 8];
                a[2] = yk[4 * YS_STRIDE + vb];
                a[3] = yk[4 * YS_STRIDE + vb + 8];
                #pragma unroll
                for (int r = 0; r < 4; r++) {
                    Ah[mt][r] = tf32_rna(a[r]);
                    Al[mt][r] = tf32_rna(a[r] - __uint_as_float(Ah[mt][r]));
                }
            }
            #pragma unroll
            for (int nt = 0; nt < 8; nt++) {
                uint32_t b0h = __float_as_uint(bf[nt].x);
                uint32_t b1h = __float_as_uint(bf[nt].y);
                uint32_t b0l = __float_as_uint(bf[nt].z);
                uint32_t b1l = __float_as_uint(bf[nt].w);
                #pragma unroll
                for (int mt = 0; mt < 2; mt++) {
                    float* c = &acc[(mt * 8 + nt) * 4];
                    mma_tf32(c, Ah[mt][0], Ah[mt][1], Ah[mt][2], Ah[mt][3], b0h, b1h);
                    mma_tf32(c, Al[mt][0], Al[mt][1], Al[mt][2], Al[mt][3], b0h, b1h);
                    mma_tf32(c, Ah[mt][0], Ah[mt][1], Ah[mt][2], Ah[mt][3], b0l, b1l);
                }
            }
        }
    };

    // ---- prologue ----
    pf_x(0);
    cm_x(xs[0]);
    __syncthreads();                 // xs(0) visible
    radial(xs[0], ysb[0]);           // Ys0 = data(0)
    pf_x(1);
    cm_x(xs[1]);
    __syncthreads();                 // Ys0 + xs(1) visible

    // ---- main loop: ONE barrier per pair; radial(p+1) || gemm(p) ----
    #pragma unroll 1
    for (int pair = 0; pair < NPAIR; pair++) {
        const int cur = pair & 1;
        if (pair + 2 < NPAIR) pf_x(pair + 2);              // LDGs in flight
        if (pair + 1 < NPAIR)
            radial(xs[(pair + 1) & 1], ysb[cur ^ 1]);      // LSU-heavy
        gemm(pair, ysb[cur]);                              // tensor-heavy
        if (pair + 2 < NPAIR) cm_x(xs[pair & 1]);          // commit halo(p+2)
        __syncthreads();
    }

    // ---- epilogue: stage through smem (aliases ysb[0]) for coalesced stores ----
    float* stage = ysb[0];
    #pragma unroll 1
    for (int chunk = 0; chunk < 4; chunk++) {
        if (chunk) __syncthreads();
        #pragma unroll
        for (int mt = 0; mt < 2; mt++) {
            #pragma unroll
            for (int nt2 = 0; nt2 < 2; nt2++) {
                const int nt = chunk * 2 + nt2;
                #pragma unroll
                for (int r = 0; r < 4; r++) {
                    int vox = wid * 32 + mt * 16 + gid + ((r >> 1) << 3);
                    int c16 = nt2 * 8 + 2 * tidg + (r & 1);
                    stage[c16 * YS_STRIDE + vox] = acc[(mt * 8 + nt) * 4 + r];
                }
            }
        }
        __syncthreads();
        #pragma unroll
        for (int j = 0; j < 4; j++) {
            const int o16  = j * 4 + wid;
            const int row  = lid >> 1;
            const int half = lid & 1;
            const int o    = chunk * 16 + o16;
            const float bb = __ldg(&bias[o]);
            float4 v = *(float4*)&stage[o16 * YS_STRIDE + row * 8 + half * 4];
            v.x += bb; v.y += bb; v.z += bb; v.w += bb;
            const int gz = z0 + (row >> 3), gy = y0 + (row & 7);
            float* dst = out + ((size_t)b * NO + o) * x_chan
                             + ((size_t)gz * DIMS + gy) * DIMS + x0 + half * 4;
            *(float4*)dst = v;
        }
    }
}

extern "C" void kernel_launch(void* const* d_in, const int* in_sizes, int n_in,
                              void* d_out, int out_size)
{
    const float* x    = (const float*)d_in[0];   // [2,32,1,48,48,48]
    const float* w    = (const float*)d_in[1];   // [64,32,1,1,1,10]
    const float* bias = (const float*)d_in[2];   // [64]
    float* out = (float*)d_out;                  // [2,64,1,48,48,48]

    bprep_kernel<<<(NPAIR * 3 * 8 * 32 + 255) / 256, 256>>>(w);

    cudaFuncSetAttribute(econv_kernel,
                         cudaFuncAttributeMaxDynamicSharedMemorySize, SMEM_BYTES);
    dim3 grid(864, 2);   // 6x6x24 spatial tiles x batch
    econv_kernel<<<grid, NTHR, SMEM_BYTES>>>(x, bias, out);
}

// round 11
// speedup vs baseline: 1.4232x; 1.3701x over previous
#include <cuda_runtime.h>
#include <cstdint>

// EquiLocalPatOrientConvolution: B=2, I=32, O=64, D=H=W=48, K=5 (pad 2).
// v11 = v8 structure (2 bars/iter, phase-pure regions, 4 blocks/SM) with
// QUAD channel packing: float4 halo, 125 LDS.128 radial, K=40 = 5 exact k8
// mma steps (no pad waste). tf32 3x-split mma, rel_err ~3e-6.

#define DIMS  48
#define TX    8
#define TY    8
#define TZ    2
#define HX    12
#define HY    12
#define HZ    6
#define NI    32
#define NO    64
#define NP    10
#define Y0C   0.28209479177387814f
#define NTHR  128
#define NQUAD 8
#define NKS   5                          // k8 steps per quad (K=40)

#define XS_CELLS   (HZ * HY * HX)        // 864 float4 cells per buffer
#define YS_STRIDE  136                   // 128 vox + 8 pad
#define YS_ROWS    40                    // K=40, exact
#define YS_FLOATS  (YS_ROWS * YS_STRIDE)
#define SMEM_FLOATS (2 * 4 * XS_CELLS + YS_FLOATS)
#define SMEM_BYTES  (SMEM_FLOATS * 4 + 256)   // ~49.7 KB -> 4 blocks/SM

__device__ __host__ constexpr int p_of_r2(int r2) {
    return r2 <= 6 ? r2 : (r2 == 8 ? 7 : (r2 == 9 ? 8 : 9));
}

// B fragments: [quad][ks][nt][lane] -> float4 {b0hi, b1hi, b0lo, b1lo}
__device__ float4 g_Bf[NQUAD * NKS * 8 * 32];

__device__ __forceinline__ uint32_t tf32_rna(float x) {
    uint32_t r;
    asm("cvt.rna.tf32.f32 %0, %1;" : "=r"(r) : "f"(x));
    return r;
}

__device__ __forceinline__ void mma_tf32(float* c,
                                         uint32_t a0, uint32_t a1, uint32_t a2, uint32_t a3,
                                         uint32_t b0, uint32_t b1) {
    asm("mma.sync.aligned.m16n8k8.row.col.f32.tf32.tf32.f32 "
        "{%0,%1,%2,%3}, {%4,%5,%6,%7}, {%8,%9}, {%0,%1,%2,%3};"
        : "+f"(c[0]), "+f"(c[1]), "+f"(c[2]), "+f"(c[3])
        : "r"(a0), "r"(a1), "r"(a2), "r"(a3), "r"(b0), "r"(b1));
}

// ---------- prep: W[o][ci][p] -> B-fragment layout, Y0 folded, hi/lo tf32 ----------
__global__ void bprep_kernel(const float* __restrict__ wg) {
    int idx = blockIdx.x * 256 + threadIdx.x;
    if (idx >= NQUAD * NKS * 8 * 32) return;
    int lane = idx & 31;
    int r    = idx >> 5;
    int nt   = r & 7;  r >>= 3;
    int ks   = r % NKS;
    int quad = r / NKS;
    int gid = lane >> 2, tidg = lane & 3;
    int o = nt * 8 + gid;
    auto getw = [&](int k) -> float {        // k in 0..39
        int ci = quad * 4 + k / 10;
        int p  = k % 10;
        return Y0C * wg[o * (NI * NP) + ci * NP + p];
    };
    float b0 = getw(ks * 8 + tidg);
    float b1 = getw(ks * 8 + tidg + 4);
    uint32_t b0h = tf32_rna(b0), b1h = tf32_rna(b1);
    uint32_t b0l = tf32_rna(b0 - __uint_as_float(b0h));
    uint32_t b1l = tf32_rna(b1 - __uint_as_float(b1h));
    g_Bf[idx] = make_float4(__uint_as_float(b0h), __uint_as_float(b1h),
                            __uint_as_float(b0l), __uint_as_float(b1l));
}

// ---------- main ----------
__global__ void __launch_bounds__(NTHR, 4)
econv_kernel(const float* __restrict__ x,
             const float* __restrict__ bias,
             float* __restrict__ out)
{
    extern __shared__ float smem[];
    float4* xs[2];
    xs[0] = (float4*)smem;
    xs[1] = xs[0] + XS_CELLS;
    float* Ys = smem + 8 * XS_CELLS;            // [k][vox], stride YS_STRIDE

    const int tid  = threadIdx.x;
    const int wid  = tid >> 5;
    const int lid  = tid & 31;
    const int gid  = lid >> 2;
    const int tidg = lid & 3;
    const int b    = blockIdx.y;
    const int t    = blockIdx.x;                // 6x6x24
    const int tz   = t / 36;
    const int ty   = (t % 36) / 6;
    const int tx   = t % 6;
    const int z0   = tz * TZ, y0 = ty * TY, x0 = tx * TX;

    const size_t x_chan = (size_t)DIMS * DIMS * DIMS;
    const float* xb = x + (size_t)b * NI * x_chan;

    float acc[64];
    #pragma unroll
    for (int k = 0; k < 64; k++) acc[k] = 0.0f;

    // ---- halo prefetch + commit for a quad (4 channels) ----
    // Kept adjacent (pf then cm) so no long register live-range across gemm.
    auto load_quad = [&](int quad, float4* dst) {
        const float* c0 = xb + (size_t)(4 * quad) * x_chan;
        float4 pre[7];
        #pragma unroll
        for (int k = 0; k < 7; k++) {
            int idx = tid + k * NTHR;
            float4 v = make_float4(0.f, 0.f, 0.f, 0.f);
            if (idx < XS_CELLS) {
                int zz = idx / (HX * HY);
                int rr = idx % (HX * HY);
                int yy = rr / HX, xx = rr % HX;
                int gz = z0 + zz - 2, gy = y0 + yy - 2, gx = x0 + xx - 2;
                if ((unsigned)gz < (unsigned)DIMS &&
                    (unsigned)gy < (unsigned)DIMS &&
                    (unsigned)gx < (unsigned)DIMS) {
                    size_t off = ((size_t)gz * DIMS + gy) * DIMS + gx;
                    v.x = __ldg(&c0[off]);
                    v.y = __ldg(&c0[off + x_chan]);
                    v.z = __ldg(&c0[off + 2 * x_chan]);
                    v.w = __ldg(&c0[off + 3 * x_chan]);
                }
            }
            pre[k] = v;
        }
        #pragma unroll
        for (int k = 0; k < 7; k++) {
            int idx = tid + k * NTHR;
            if (idx < XS_CELLS) dst[idx] = pre[k];   // STS.128, conflict-free
        }
    };

    // ---- radial sums for 4 channels (125 LDS.128 + 250 f32x2 adds) ----
    auto radial = [&](const float4* xsrc) {
        const int vz = tid >> 6, vy = (tid >> 3) & 7, vx = tid & 7;
        unsigned long long y01[NP], y23[NP];
        #pragma unroll
        for (int p = 0; p < NP; p++) { y01[p] = 0ULL; y23[p] = 0ULL; }
        #pragma unroll
        for (int dz = 0; dz < 5; dz++) {
            #pragma unroll
            for (int dy = 0; dy < 5; dy++) {
                const float4* row = &xsrc[((vz + dz) * HY + (vy + dy)) * HX + vx];
                #pragma unroll
                for (int dx = 0; dx < 5; dx++) {
                    const int p = p_of_r2((dz - 2) * (dz - 2) +
                                          (dy - 2) * (dy - 2) +
                                          (dx - 2) * (dx - 2));
                    union { float4 f; unsigned long long u[2]; } c;
                    c.f = row[dx];                    // LDS.128, conflict-free
                    asm("add.rn.f32x2 %0, %0, %1;" : "+l"(y01[p]) : "l"(c.u[0]));
                    asm("add.rn.f32x2 %0, %0, %1;" : "+l"(y23[p]) : "l"(c.u[1]));
                }
            }
        }
        #pragma unroll
        for (int p = 0; p < NP; p++) {
            float2 a = *(float2*)&y01[p];
            float2 d = *(float2*)&y23[p];
            Ys[p * YS_STRIDE + tid]        = a.x;   // ch0 -> k rows 0..9
            Ys[(p + 10) * YS_STRIDE + tid] = a.y;   // ch1 -> k rows 10..19
            Ys[(p + 20) * YS_STRIDE + tid] = d.x;   // ch2 -> k rows 20..29
            Ys[(p + 30) * YS_STRIDE + tid] = d.y;   // ch3 -> k rows 30..39
        }
    };

    // ---- GEMM: 3xTF32 mma over this quad's K=40 (5 exact k8 steps) ----
    auto gemm = [&](int quad) {
        const float4* bsrc = g_Bf + quad * (NKS * 8 * 32);
        #pragma unroll
        for (int ks = 0; ks < NKS; ks++) {
            uint32_t Ah[2][4], Al[2][4];
            #pragma unroll
            for (int mt = 0; mt < 2; mt++) {
                const int vb = wid * 32 + mt * 16 + gid;
                const float* yk = Ys + (ks * 8 + tidg) * YS_STRIDE;
                float a[4];
                a[0] = yk[vb];
                a[1] = yk[vb + 8];
                a[2] = yk[4 * YS_STRIDE + vb];
                a[3] = yk[4 * YS_STRIDE + vb + 8];
                #pragma unroll
                for (int r = 0; r < 4; r++) {
                    Ah[mt][r] = tf32_rna(a[r]);
                    Al[mt][r] = tf32_rna(a[r] - __uint_as_float(Ah[mt][r]));
                }
            }
            #pragma unroll
            for (int nt = 0; nt < 8; nt++) {
                float4 bf = __ldg(&bsrc[(ks * 8 + nt) * 32 + lid]);
                uint32_t b0h = __float_as_uint(bf.x);
                uint32_t b1h = __float_as_uint(bf.y);
                uint32_t b0l = __float_as_uint(bf.z);
                uint32_t b1l = __float_as_uint(bf.w);
                #pragma unroll
                for (int mt = 0; mt < 2; mt++) {
                    float* c = &acc[(mt * 8 + nt) * 4];
                    mma_tf32(c, Ah[mt][0], Ah[mt][1], Ah[mt][2], Ah[mt][3], b0h, b1h);
                    mma_tf32(c, Al[mt][0], Al[mt][1], Al[mt][2], Al[mt][3], b0h, b1h);
                    mma_tf32(c, Ah[mt][0], Ah[mt][1], Ah[mt][2], Ah[mt][3], b0l, b1l);
                }
            }
        }
    };

    // ---- prologue ----
    load_quad(0, xs[0]);
    __syncthreads();                 // xs(0) visible
    radial(xs[0]);                   // Ys(0)

    // ---- main loop over 8 quads (v8 discipline: 2 bars/iter, pure phases) ----
    #pragma unroll 1
    for (int q = 0; q < NQUAD; q++) {
        __syncthreads();             // Ys(q) visible
        gemm(q);
        if (q + 1 < NQUAD) {
            load_quad(q + 1, xs[(q + 1) & 1]);
            __syncthreads();         // xs(q+1) visible; gemm done with Ys
            radial(xs[(q + 1) & 1]); // Ys(q+1)
        }
    }

    // ---- epilogue: stage through smem (aliases Ys) for coalesced stores ----
    __syncthreads();
    float* stage = Ys;
    #pragma unroll 1
    for (int chunk = 0; chunk < 4; chunk++) {
        if (chunk) __syncthreads();
        #pragma unroll
        for (int mt = 0; mt < 2; mt++) {
            #pragma unroll
            for (int nt2 = 0; nt2 < 2; nt2++) {
                const int nt = chunk * 2 + nt2;
                #pragma unroll
                for (int r = 0; r < 4; r++) {
                    int vox = wid * 32 + mt * 16 + gid + ((r >> 1) << 3);
                    int c16 = nt2 * 8 + 2 * tidg + (r & 1);
                    stage[c16 * YS_STRIDE + vox] = acc[(mt * 8 + nt) * 4 + r];
                }
            }
        }
        __syncthreads();
        #pragma unroll
        for (int j = 0; j < 4; j++) {
            const int o16  = j * 4 + wid;
            const int row  = lid >> 1;
            const int half = lid & 1;
            const int o    = chunk * 16 + o16;
            const float bb = __ldg(&bias[o]);
            float4 v = *(float4*)&stage[o16 * YS_STRIDE + row * 8 + half * 4];
            v.x += bb; v.y += bb; v.z += bb; v.w += bb;
            const int gz = z0 + (row >> 3), gy = y0 + (row & 7);
            float* dst = out + ((size_t)b * NO + o) * x_chan
                             + ((size_t)gz * DIMS + gy) * DIMS + x0 + half * 4;
            *(float4*)dst = v;
        }
    }
}

extern "C" void kernel_launch(void* const* d_in, const int* in_sizes, int n_in,
                              void* d_out, int out_size)
{
    const float* x    = (const float*)d_in[0];   // [2,32,1,48,48,48]
    const float* w    = (const float*)d_in[1];   // [64,32,1,1,1,10]
    const float* bias = (const float*)d_in[2];   // [64]
    float* out = (float*)d_out;                  // [2,64,1,48,48,48]

    bprep_kernel<<<(NQUAD * NKS * 8 * 32 + 255) / 256, 256>>>(w);

    cudaFuncSetAttribute(econv_kernel,
                         cudaFuncAttributeMaxDynamicSharedMemorySize, SMEM_BYTES);
    dim3 grid(864, 2);   // 6x6x24 spatial tiles x batch
    econv_kernel<<<grid, NTHR, SMEM_BYTES>>>(x, bias, out);
}

// round 12
// speedup vs baseline: 1.5737x; 1.1058x over previous
#include <cuda_runtime.h>
#include <cstdint>

// EquiLocalPatOrientConvolution: B=2, I=32, O=64, D=H=W=48, K=5 (pad 2).
// v12 = v11 (quad channel packing, float4 halo, 125 LDS.128 radial, K=40 =
// 5 exact k8 steps) with 2-split tf32 mma (AhBh + AlBh; AhBl dropped).
// Expected rel_err ~1.5e-4 (<1e-3). 4 blocks/SM.

#define DIMS  48
#define TX    8
#define TY    8
#define TZ    2
#define HX    12
#define HY    12
#define HZ    6
#define NI    32
#define NO    64
#define NP    10
#define Y0C   0.28209479177387814f
#define NTHR  128
#define NQUAD 8
#define NKS   5                          // k8 steps per quad (K=40)

#define XS_CELLS   (HZ * HY * HX)        // 864 float4 cells per buffer
#define YS_STRIDE  136                   // 128 vox + 8 pad
#define YS_ROWS    40                    // K=40, exact
#define YS_FLOATS  (YS_ROWS * YS_STRIDE)
#define SMEM_FLOATS (2 * 4 * XS_CELLS + YS_FLOATS)
#define SMEM_BYTES  (SMEM_FLOATS * 4 + 256)   // ~49.7 KB -> 4 blocks/SM

__device__ __host__ constexpr int p_of_r2(int r2) {
    return r2 <= 6 ? r2 : (r2 == 8 ? 7 : (r2 == 9 ? 8 : 9));
}

// B fragments: [quad][ks][nt][lane] -> float2 {b0hi, b1hi}
__device__ float2 g_Bf[NQUAD * NKS * 8 * 32];

__device__ __forceinline__ uint32_t tf32_rna(float x) {
    uint32_t r;
    asm("cvt.rna.tf32.f32 %0, %1;" : "=r"(r) : "f"(x));
    return r;
}

__device__ __forceinline__ void mma_tf32(float* c,
                                         uint32_t a0, uint32_t a1, uint32_t a2, uint32_t a3,
                                         uint32_t b0, uint32_t b1) {
    asm("mma.sync.aligned.m16n8k8.row.col.f32.tf32.tf32.f32 "
        "{%0,%1,%2,%3}, {%4,%5,%6,%7}, {%8,%9}, {%0,%1,%2,%3};"
        : "+f"(c[0]), "+f"(c[1]), "+f"(c[2]), "+f"(c[3])
        : "r"(a0), "r"(a1), "r"(a2), "r"(a3), "r"(b0), "r"(b1));
}

// ---------- prep: W[o][ci][p] -> B-fragment layout, Y0 folded, hi tf32 ----------
__global__ void bprep_kernel(const float* __restrict__ wg) {
    int idx = blockIdx.x * 256 + threadIdx.x;
    if (idx >= NQUAD * NKS * 8 * 32) return;
    int lane = idx & 31;
    int r    = idx >> 5;
    int nt   = r & 7;  r >>= 3;
    int ks   = r % NKS;
    int quad = r / NKS;
    int gid = lane >> 2, tidg = lane & 3;
    int o = nt * 8 + gid;
    auto getw = [&](int k) -> float {        // k in 0..39
        int ci = quad * 4 + k / 10;
        int p  = k % 10;
        return Y0C * wg[o * (NI * NP) + ci * NP + p];
    };
    float b0 = getw(ks * 8 + tidg);
    float b1 = getw(ks * 8 + tidg + 4);
    uint32_t b0h = tf32_rna(b0), b1h = tf32_rna(b1);
    g_Bf[idx] = make_float2(__uint_as_float(b0h), __uint_as_float(b1h));
}

// ---------- main ----------
__global__ void __launch_bounds__(NTHR, 4)
econv_kernel(const float* __restrict__ x,
             const float* __restrict__ bias,
             float* __restrict__ out)
{
    extern __shared__ float smem[];
    float4* xs[2];
    xs[0] = (float4*)smem;
    xs[1] = xs[0] + XS_CELLS;
    float* Ys = smem + 8 * XS_CELLS;            // [k][vox], stride YS_STRIDE

    const int tid  = threadIdx.x;
    const int wid  = tid >> 5;
    const int lid  = tid & 31;
    const int gid  = lid >> 2;
    const int tidg = lid & 3;
    const int b    = blockIdx.y;
    const int t    = blockIdx.x;                // 6x6x24
    const int tz   = t / 36;
    const int ty   = (t % 36) / 6;
    const int tx   = t % 6;
    const int z0   = tz * TZ, y0 = ty * TY, x0 = tx * TX;

    const size_t x_chan = (size_t)DIMS * DIMS * DIMS;
    const float* xb = x + (size_t)b * NI * x_chan;

    float acc[64];
    #pragma unroll
    for (int k = 0; k < 64; k++) acc[k] = 0.0f;

    // ---- halo prefetch + commit for a quad (4 channels) ----
    auto load_quad = [&](int quad, float4* dst) {
        const float* c0 = xb + (size_t)(4 * quad) * x_chan;
        float4 pre[7];
        #pragma unroll
        for (int k = 0; k < 7; k++) {
            int idx = tid + k * NTHR;
            float4 v = make_float4(0.f, 0.f, 0.f, 0.f);
            if (idx < XS_CELLS) {
                int zz = idx / (HX * HY);
                int rr = idx % (HX * HY);
                int yy = rr / HX, xx = rr % HX;
                int gz = z0 + zz - 2, gy = y0 + yy - 2, gx = x0 + xx - 2;
                if ((unsigned)gz < (unsigned)DIMS &&
                    (unsigned)gy < (unsigned)DIMS &&
                    (unsigned)gx < (unsigned)DIMS) {
                    size_t off = ((size_t)gz * DIMS + gy) * DIMS + gx;
                    v.x = __ldg(&c0[off]);
                    v.y = __ldg(&c0[off + x_chan]);
                    v.z = __ldg(&c0[off + 2 * x_chan]);
                    v.w = __ldg(&c0[off + 3 * x_chan]);
                }
            }
            pre[k] = v;
        }
        #pragma unroll
        for (int k = 0; k < 7; k++) {
            int idx = tid + k * NTHR;
            if (idx < XS_CELLS) dst[idx] = pre[k];   // STS.128, conflict-free
        }
    };

    // ---- radial sums for 4 channels (125 LDS.128 + 250 f32x2 adds) ----
    auto radial = [&](const float4* xsrc) {
        const int vz = tid >> 6, vy = (tid >> 3) & 7, vx = tid & 7;
        unsigned long long y01[NP], y23[NP];
        #pragma unroll
        for (int p = 0; p < NP; p++) { y01[p] = 0ULL; y23[p] = 0ULL; }
        #pragma unroll
        for (int dz = 0; dz < 5; dz++) {
            #pragma unroll
            for (int dy = 0; dy < 5; dy++) {
                const float4* row = &xsrc[((vz + dz) * HY + (vy + dy)) * HX + vx];
                #pragma unroll
                for (int dx = 0; dx < 5; dx++) {
                    const int p = p_of_r2((dz - 2) * (dz - 2) +
                                          (dy - 2) * (dy - 2) +
                                          (dx - 2) * (dx - 2));
                    union { float4 f; unsigned long long u[2]; } c;
                    c.f = row[dx];                    // LDS.128, conflict-free
                    asm("add.rn.f32x2 %0, %0, %1;" : "+l"(y01[p]) : "l"(c.u[0]));
                    asm("add.rn.f32x2 %0, %0, %1;" : "+l"(y23[p]) : "l"(c.u[1]));
                }
            }
        }
        #pragma unroll
        for (int p = 0; p < NP; p++) {
            float2 a = *(float2*)&y01[p];
            float2 d = *(float2*)&y23[p];
            Ys[p * YS_STRIDE + tid]        = a.x;   // ch0 -> k rows 0..9
            Ys[(p + 10) * YS_STRIDE + tid] = a.y;   // ch1 -> k rows 10..19
            Ys[(p + 20) * YS_STRIDE + tid] = d.x;   // ch2 -> k rows 20..29
            Ys[(p + 30) * YS_STRIDE + tid] = d.y;   // ch3 -> k rows 30..39
        }
    };

    // ---- GEMM: 2-split tf32 mma over this quad's K=40 (5 exact k8 steps) ----
    auto gemm = [&](int quad) {
        const float2* bsrc = g_Bf + quad * (NKS * 8 * 32);
        #pragma unroll
        for (int ks = 0; ks < NKS; ks++) {
            uint32_t Ah[2][4], Al[2][4];
            #pragma unroll
            for (int mt = 0; mt < 2; mt++) {
                const int vb = wid * 32 + mt * 16 + gid;
                const float* yk = Ys + (ks * 8 + tidg) * YS_STRIDE;
                float a[4];
                a[0] = yk[vb];
                a[1] = yk[vb + 8];
                a[2] = yk[4 * YS_STRIDE + vb];
                a[3] = yk[4 * YS_STRIDE + vb + 8];
                #pragma unroll
                for (int r = 0; r < 4; r++) {
                    Ah[mt][r] = tf32_rna(a[r]);
                    Al[mt][r] = tf32_rna(a[r] - __uint_as_float(Ah[mt][r]));
                }
            }
            #pragma unroll
            for (int nt = 0; nt < 8; nt++) {
                float2 bf = __ldg(&bsrc[(ks * 8 + nt) * 32 + lid]);
                uint32_t b0h = __float_as_uint(bf.x);
                uint32_t b1h = __float_as_uint(bf.y);
                #pragma unroll
                for (int mt = 0; mt < 2; mt++) {
                    float* c = &acc[(mt * 8 + nt) * 4];
                    mma_tf32(c, Ah[mt][0], Ah[mt][1], Ah[mt][2], Ah[mt][3], b0h, b1h);
                    mma_tf32(c, Al[mt][0], Al[mt][1], Al[mt][2], Al[mt][3], b0h, b1h);
                }
            }
        }
    };

    // ---- prologue ----
    load_quad(0, xs[0]);
    __syncthreads();                 // xs(0) visible
    radial(xs[0]);                   // Ys(0)

    // ---- main loop over 8 quads (2 bars/iter, phase-pure regions) ----
    #pragma unroll 1
    for (int q = 0; q < NQUAD; q++) {
        __syncthreads();             // Ys(q) visible
        gemm(q);
        if (q + 1 < NQUAD) {
            load_quad(q + 1, xs[(q + 1) & 1]);
            __syncthreads();         // xs(q+1) visible; gemm done with Ys
            radial(xs[(q + 1) & 1]); // Ys(q+1)
        }
    }

    // ---- epilogue: stage through smem (aliases Ys) for coalesced stores ----
    __syncthreads();
    float* stage = Ys;
    #pragma unroll 1
    for (int chunk = 0; chunk < 4; chunk++) {
        if (chunk) __syncthreads();
        #pragma unroll
        for (int mt = 0; mt < 2; mt++) {
            #pragma unroll
            for (int nt2 = 0; nt2 < 2; nt2++) {
                const int nt = chunk * 2 + nt2;
                #pragma unroll
                for (int r = 0; r < 4; r++) {
                    int vox = wid * 32 + mt * 16 + gid + ((r >> 1) << 3);
                    int c16 = nt2 * 8 + 2 * tidg + (r & 1);
                    stage[c16 * YS_STRIDE + vox] = acc[(mt * 8 + nt) * 4 + r];
                }
            }
        }
        __syncthreads();
        #pragma unroll
        for (int j = 0; j < 4; j++) {
            const int o16  = j * 4 + wid;
            const int row  = lid >> 1;
            const int half = lid & 1;
            const int o    = chunk * 16 + o16;
            const float bb = __ldg(&bias[o]);
            float4 v = *(float4*)&stage[o16 * YS_STRIDE + row * 8 + half * 4];
            v.x += bb; v.y += bb; v.z += bb; v.w += bb;
            const int gz = z0 + (row >> 3), gy = y0 + (row & 7);
            float* dst = out + ((size_t)b * NO + o) * x_chan
                             + ((size_t)gz * DIMS + gy) * DIMS + x0 + half * 4;
            *(float4*)dst = v;
        }
    }
}

extern "C" void kernel_launch(void* const* d_in, const int* in_sizes, int n_in,
                              void* d_out, int out_size)
{
    const float* x    = (const float*)d_in[0];   // [2,32,1,48,48,48]
    const float* w    = (const float*)d_in[1];   // [64,32,1,1,1,10]
    const float* bias = (const float*)d_in[2];   // [64]
    float* out = (float*)d_out;                  // [2,64,1,48,48,48]

    bprep_kernel<<<(NQUAD * NKS * 8 * 32 + 255) / 256, 256>>>(w);

    cudaFuncSetAttribute(econv_kernel,
                         cudaFuncAttributeMaxDynamicSharedMemorySize, SMEM_BYTES);
    dim3 grid(864, 2);   // 6x6x24 spatial tiles x batch
    econv_kernel<<<grid, NTHR, SMEM_BYTES>>>(x, bias, out);
}